// round 2
// baseline (speedup 1.0000x reference)
#include <cuda_runtime.h>

#define NC 7
#define BATCH 4194304
#define TPB 256
#define RPT 4
#define NBLK (BATCH / (TPB * RPT))   // 4096

// Per-block partials: [0]=ce, [1]=focal_w, [2]=ordinal, [3]=wasserstein
__device__ float g_part[4][NBLK];

__global__ void __launch_bounds__(TPB) fow_main(const float* __restrict__ x,
                                                const int* __restrict__ tgt)
{
    const int tid = threadIdx.x;
    const long long base = ((long long)blockIdx.x * TPB + tid) * RPT;   // row index, multiple of 4

    // ---- load 4 rows (28 floats) as 7x float4, and 4 int32 targets as 1x int4 ----
    const float4* xv = reinterpret_cast<const float4*>(x + base * NC);  // 112B-aligned
    float4 v0 = xv[0], v1 = xv[1], v2 = xv[2], v3 = xv[3], v4 = xv[4], v5 = xv[5], v6 = xv[6];
    const int4 ta = *reinterpret_cast<const int4*>(tgt + base);         // 16B-aligned

    float f[28];
    *reinterpret_cast<float4*>(f +  0) = v0;
    *reinterpret_cast<float4*>(f +  4) = v1;
    *reinterpret_cast<float4*>(f +  8) = v2;
    *reinterpret_cast<float4*>(f + 12) = v3;
    *reinterpret_cast<float4*>(f + 16) = v4;
    *reinterpret_cast<float4*>(f + 20) = v5;
    *reinterpret_cast<float4*>(f + 24) = v6;
    const int t4[4] = { ta.x, ta.y, ta.z, ta.w };

    float s_ce = 0.f, s_fw = 0.f, s_ord = 0.f, s_ws = 0.f;

    #pragma unroll
    for (int r = 0; r < RPT; r++) {
        const int tr = t4[r];
        float row[NC];
        #pragma unroll
        for (int j = 0; j < NC; j++) row[j] = f[r * NC + j];

        float m = row[0];
        #pragma unroll
        for (int j = 1; j < NC; j++) m = fmaxf(m, row[j]);

        float e[NC];
        float Z = 0.f, sxm = 0.f, xt = 0.f, et = 0.f;
        #pragma unroll
        for (int j = 0; j < NC; j++) {
            float d  = row[j] - m;
            float ej = __expf(d);
            e[j] = ej;
            Z   += ej;
            sxm += d;
            if (j == tr) { xt = d; et = ej; }   // predicated select, no spill
        }

        const float invZ = 1.0f / Z;
        const float logZ = __logf(Z);

        // CE with label smoothing 0.1 over 7 classes
        float ce = logZ - 0.0142857142857142857f * sxm - 0.9f * xt;
        s_ce += ce;

        // focal weight (scalar-ce quirk factors out of this sum)
        float pt  = et * invZ;
        float omp = 1.0f - pt;
        s_fw += 0.25f * omp * omp;

        // ordinal + wasserstein via prefix sums of e
        float S = 0.f, ws = 0.f, od = 0.f;
        #pragma unroll
        for (int j = 0; j < NC; j++) {
            S  += e[j];
            ws += (j >= tr) ? (Z - S) : S;
            od += fabsf((float)(j - tr)) * e[j];
        }
        s_ord += od * invZ;
        s_ws  += ws * invZ;
    }

    // ---- block reduction (deterministic) ----
    #pragma unroll
    for (int off = 16; off > 0; off >>= 1) {
        s_ce  += __shfl_down_sync(0xffffffffu, s_ce,  off);
        s_fw  += __shfl_down_sync(0xffffffffu, s_fw,  off);
        s_ord += __shfl_down_sync(0xffffffffu, s_ord, off);
        s_ws  += __shfl_down_sync(0xffffffffu, s_ws,  off);
    }

    __shared__ float sm[4][TPB / 32];
    const int w = tid >> 5, l = tid & 31;
    if (l == 0) { sm[0][w] = s_ce; sm[1][w] = s_fw; sm[2][w] = s_ord; sm[3][w] = s_ws; }
    __syncthreads();

    if (tid < 32) {
        const int nw = TPB / 32;
        float a = (tid < nw) ? sm[0][tid] : 0.f;
        float b = (tid < nw) ? sm[1][tid] : 0.f;
        float c = (tid < nw) ? sm[2][tid] : 0.f;
        float d = (tid < nw) ? sm[3][tid] : 0.f;
        #pragma unroll
        for (int off = 4; off > 0; off >>= 1) {
            a += __shfl_down_sync(0xffffffffu, a, off);
            b += __shfl_down_sync(0xffffffffu, b, off);
            c += __shfl_down_sync(0xffffffffu, c, off);
            d += __shfl_down_sync(0xffffffffu, d, off);
        }
        if (tid == 0) {
            g_part[0][blockIdx.x] = a;
            g_part[1][blockIdx.x] = b;
            g_part[2][blockIdx.x] = c;
            g_part[3][blockIdx.x] = d;
        }
    }
}

__global__ void __launch_bounds__(TPB) fow_final(float* __restrict__ out)
{
    const int tid = threadIdx.x;
    double s0 = 0.0, s1 = 0.0, s2 = 0.0, s3 = 0.0;
    for (int i = tid; i < NBLK; i += TPB) {
        s0 += (double)g_part[0][i];
        s1 += (double)g_part[1][i];
        s2 += (double)g_part[2][i];
        s3 += (double)g_part[3][i];
    }
    __shared__ double sh[4][TPB];
    sh[0][tid] = s0; sh[1][tid] = s1; sh[2][tid] = s2; sh[3][tid] = s3;
    __syncthreads();
    for (int off = TPB / 2; off > 0; off >>= 1) {
        if (tid < off) {
            sh[0][tid] += sh[0][tid + off];
            sh[1][tid] += sh[1][tid + off];
            sh[2][tid] += sh[2][tid + off];
            sh[3][tid] += sh[3][tid + off];
        }
        __syncthreads();
    }
    if (tid == 0) {
        const double invB = 1.0 / (double)BATCH;
        double ce = sh[0][0] * invB;
        double fw = sh[1][0] * invB;
        double od = sh[2][0] * invB;
        double ws = sh[3][0] * invB;
        out[0] = (float)(ce * fw + 0.3 * od + 0.4 * ws);
    }
}

extern "C" void kernel_launch(void* const* d_in, const int* in_sizes, int n_in,
                              void* d_out, int out_size)
{
    const float* x   = (const float*)d_in[0];
    const int*   tgt = (const int*)d_in[1];
    float*       out = (float*)d_out;

    fow_main<<<NBLK, TPB>>>(x, tgt);
    fow_final<<<1, TPB>>>(out);
}

// round 4
// speedup vs baseline: 1.1845x; 1.1845x over previous
#include <cuda_runtime.h>

#define NC 7
#define BATCH 4194304
#define TPB 256
#define RPT 4
#define NBLK (BATCH / (TPB * RPT))   // 4096
#define FTPB 1024                    // finalize threads

// Per-block partials packed: x=ce, y=focal_w, z=ordinal, w=wasserstein
__device__ float4 g_part4[NBLK];

__global__ void __launch_bounds__(TPB) fow_main(const float* __restrict__ x,
                                                const int* __restrict__ tgt)
{
    const int tid = threadIdx.x;
    const long long base = ((long long)blockIdx.x * TPB + tid) * RPT;   // row index, multiple of 4

    // ---- load 4 rows (28 floats) as 7x float4, and 4 int32 targets as 1x int4 ----
    const float4* xv = reinterpret_cast<const float4*>(x + base * NC);  // 112B-aligned
    float4 v0 = xv[0], v1 = xv[1], v2 = xv[2], v3 = xv[3], v4 = xv[4], v5 = xv[5], v6 = xv[6];
    const int4 ta = *reinterpret_cast<const int4*>(tgt + base);         // 16B-aligned

    float f[28];
    *reinterpret_cast<float4*>(f +  0) = v0;
    *reinterpret_cast<float4*>(f +  4) = v1;
    *reinterpret_cast<float4*>(f +  8) = v2;
    *reinterpret_cast<float4*>(f + 12) = v3;
    *reinterpret_cast<float4*>(f + 16) = v4;
    *reinterpret_cast<float4*>(f + 20) = v5;
    *reinterpret_cast<float4*>(f + 24) = v6;
    const int t4[4] = { ta.x, ta.y, ta.z, ta.w };

    float s_ce = 0.f, s_fw = 0.f, s_ord = 0.f, s_ws = 0.f;

    #pragma unroll
    for (int r = 0; r < RPT; r++) {
        const int tr = t4[r];
        float row[NC];
        #pragma unroll
        for (int j = 0; j < NC; j++) row[j] = f[r * NC + j];

        float m = row[0];
        #pragma unroll
        for (int j = 1; j < NC; j++) m = fmaxf(m, row[j]);

        float e[NC];
        float Z = 0.f, sxm = 0.f, xt = 0.f, et = 0.f;
        #pragma unroll
        for (int j = 0; j < NC; j++) {
            float d  = row[j] - m;
            float ej = __expf(d);
            e[j] = ej;
            Z   += ej;
            sxm += d;
            if (j == tr) { xt = d; et = ej; }   // predicated select, no spill
        }

        const float invZ = 1.0f / Z;
        const float logZ = __logf(Z);

        // CE with label smoothing 0.1 over 7 classes
        float ce = logZ - 0.0142857142857142857f * sxm - 0.9f * xt;
        s_ce += ce;

        // focal weight (scalar-ce quirk factors out of this sum)
        float pt  = et * invZ;
        float omp = 1.0f - pt;
        s_fw += 0.25f * omp * omp;

        // ordinal + wasserstein via prefix sums of e
        float S = 0.f, ws = 0.f, od = 0.f;
        #pragma unroll
        for (int j = 0; j < NC; j++) {
            S  += e[j];
            ws += (j >= tr) ? (Z - S) : S;
            od += fabsf((float)(j - tr)) * e[j];
        }
        s_ord += od * invZ;
        s_ws  += ws * invZ;
    }

    // ---- block reduction (deterministic) ----
    #pragma unroll
    for (int off = 16; off > 0; off >>= 1) {
        s_ce  += __shfl_down_sync(0xffffffffu, s_ce,  off);
        s_fw  += __shfl_down_sync(0xffffffffu, s_fw,  off);
        s_ord += __shfl_down_sync(0xffffffffu, s_ord, off);
        s_ws  += __shfl_down_sync(0xffffffffu, s_ws,  off);
    }

    __shared__ float sm[4][TPB / 32];
    const int w = tid >> 5, l = tid & 31;
    if (l == 0) { sm[0][w] = s_ce; sm[1][w] = s_fw; sm[2][w] = s_ord; sm[3][w] = s_ws; }
    __syncthreads();

    if (tid < 32) {
        const int nw = TPB / 32;
        float a = (tid < nw) ? sm[0][tid] : 0.f;
        float b = (tid < nw) ? sm[1][tid] : 0.f;
        float c = (tid < nw) ? sm[2][tid] : 0.f;
        float d = (tid < nw) ? sm[3][tid] : 0.f;
        #pragma unroll
        for (int off = 4; off > 0; off >>= 1) {
            a += __shfl_down_sync(0xffffffffu, a, off);
            b += __shfl_down_sync(0xffffffffu, b, off);
            c += __shfl_down_sync(0xffffffffu, c, off);
            d += __shfl_down_sync(0xffffffffu, d, off);
        }
        if (tid == 0) g_part4[blockIdx.x] = make_float4(a, b, c, d);
    }
}

__global__ void __launch_bounds__(FTPB) fow_final(float* __restrict__ out)
{
    const int tid = threadIdx.x;

    double s0 = 0.0, s1 = 0.0, s2 = 0.0, s3 = 0.0;
    #pragma unroll
    for (int i = 0; i < NBLK / FTPB; i++) {            // 4 coalesced float4 loads/thread
        float4 p = g_part4[tid + i * FTPB];
        s0 += (double)p.x; s1 += (double)p.y; s2 += (double)p.z; s3 += (double)p.w;
    }

    // warp reduce (doubles via shfl)
    #pragma unroll
    for (int off = 16; off > 0; off >>= 1) {
        s0 += __shfl_down_sync(0xffffffffu, s0, off);
        s1 += __shfl_down_sync(0xffffffffu, s1, off);
        s2 += __shfl_down_sync(0xffffffffu, s2, off);
        s3 += __shfl_down_sync(0xffffffffu, s3, off);
    }

    __shared__ double sh[4][FTPB / 32];                // 32 warps
    const int w = tid >> 5, l = tid & 31;
    if (l == 0) { sh[0][w] = s0; sh[1][w] = s1; sh[2][w] = s2; sh[3][w] = s3; }
    __syncthreads();

    if (tid < 32) {
        double a = sh[0][tid], b = sh[1][tid], c = sh[2][tid], d = sh[3][tid];
        #pragma unroll
        for (int off = 16; off > 0; off >>= 1) {
            a += __shfl_down_sync(0xffffffffu, a, off);
            b += __shfl_down_sync(0xffffffffu, b, off);
            c += __shfl_down_sync(0xffffffffu, c, off);
            d += __shfl_down_sync(0xffffffffu, d, off);
        }
        if (tid == 0) {
            const double invB = 1.0 / (double)BATCH;
            out[0] = (float)((a * invB) * (b * invB) + 0.3 * (c * invB) + 0.4 * (d * invB));
        }
    }
}

extern "C" void kernel_launch(void* const* d_in, const int* in_sizes, int n_in,
                              void* d_out, int out_size)
{
    const float* x   = (const float*)d_in[0];
    const int*   tgt = (const int*)d_in[1];
    float*       out = (float*)d_out;

    fow_main<<<NBLK, TPB>>>(x, tgt);
    fow_final<<<1, FTPB>>>(out);
}